// round 4
// baseline (speedup 1.0000x reference)
#include <cuda_runtime.h>
#include <math.h>

// ---------------- problem constants ----------------
#define BB   2
#define TT   2048
#define HH   16
#define HKVn 4
#define DD   128
#define GG   4
#define DIMn 2048           // HH*DD
#define KVD  512            // HKVn*DD
#define NTOK (BB*TT)        // 4096
#define HALF 64             // DD/2

// ---------------- device scratch (no allocs allowed) ----------------
__device__ float g_Q[(size_t)NTOK * DIMn];     // 32 MB
__device__ float g_K[(size_t)NTOK * KVD];      // 8 MB
__device__ float g_Y[(size_t)NTOK * DIMn];     // 32 MB
__device__ float g_cos[TT * HALF];
__device__ float g_sin[TT * HALF];

// ---------------- RoPE table (NTK-scaled, T > train_seq_len) ----------------
__global__ void rope_table_kernel() {
    int idx = blockIdx.x * blockDim.x + threadIdx.x;
    if (idx >= TT * HALF) return;
    int t = idx >> 6;          // token
    int i = idx & 63;          // pair index
    // base = 10000 * (T/1024)^(D/(D-2)) = 10000 * 2^(128/126)
    double base = 10000.0 * pow(2.0, 128.0 / 126.0);
    double inv  = pow(base, -((double)(2 * i)) / 128.0);
    double ang  = (double)t * inv;
    g_cos[idx] = (float)cos(ang);
    g_sin[idx] = (float)sin(ang);
}

// ---------------- SGEMM: C[M,N] = A[M,K] * B[N,K]^T (both K-contiguous) ----
// 128x128 block, BK=16, 8x8 microtile (4+4 split), 256 threads.
__global__ __launch_bounds__(256, 2)
void sgemm_nt(const float* __restrict__ A, const float* __restrict__ Bm,
              float* __restrict__ C, int M, int N, int K) {
    __shared__ __align__(16) float As[16][128];
    __shared__ __align__(16) float Bs[16][128];

    const int tid = threadIdx.x;
    const int tx = tid & 15;
    const int ty = tid >> 4;
    const int lr = tid >> 2;           // 0..63
    const int lc = (tid & 3) << 2;     // 0,4,8,12

    const float* Ab = A + (size_t)blockIdx.y * 128 * K;
    const float* Bb = Bm + (size_t)blockIdx.x * 128 * K;

    float acc[8][8];
#pragma unroll
    for (int i = 0; i < 8; i++)
#pragma unroll
        for (int j = 0; j < 8; j++) acc[i][j] = 0.f;

    for (int k0 = 0; k0 < K; k0 += 16) {
        float4 a0 = *(const float4*)(Ab + (size_t)lr * K + k0 + lc);
        float4 a1 = *(const float4*)(Ab + (size_t)(lr + 64) * K + k0 + lc);
        float4 b0 = *(const float4*)(Bb + (size_t)lr * K + k0 + lc);
        float4 b1 = *(const float4*)(Bb + (size_t)(lr + 64) * K + k0 + lc);
        __syncthreads();
        As[lc + 0][lr] = a0.x; As[lc + 1][lr] = a0.y; As[lc + 2][lr] = a0.z; As[lc + 3][lr] = a0.w;
        As[lc + 0][lr + 64] = a1.x; As[lc + 1][lr + 64] = a1.y; As[lc + 2][lr + 64] = a1.z; As[lc + 3][lr + 64] = a1.w;
        Bs[lc + 0][lr] = b0.x; Bs[lc + 1][lr] = b0.y; Bs[lc + 2][lr] = b0.z; Bs[lc + 3][lr] = b0.w;
        Bs[lc + 0][lr + 64] = b1.x; Bs[lc + 1][lr + 64] = b1.y; Bs[lc + 2][lr + 64] = b1.z; Bs[lc + 3][lr + 64] = b1.w;
        __syncthreads();
#pragma unroll
        for (int kk = 0; kk < 16; kk++) {
            float4 xa0 = *(const float4*)&As[kk][ty * 4];
            float4 xa1 = *(const float4*)&As[kk][ty * 4 + 64];
            float4 xb0 = *(const float4*)&Bs[kk][tx * 4];
            float4 xb1 = *(const float4*)&Bs[kk][tx * 4 + 64];
            float av[8] = {xa0.x, xa0.y, xa0.z, xa0.w, xa1.x, xa1.y, xa1.z, xa1.w};
            float bv[8] = {xb0.x, xb0.y, xb0.z, xb0.w, xb1.x, xb1.y, xb1.z, xb1.w};
#pragma unroll
            for (int i = 0; i < 8; i++)
#pragma unroll
                for (int j = 0; j < 8; j++) acc[i][j] += av[i] * bv[j];
        }
    }

    const int rbase = blockIdx.y * 128;
    const int cbase = blockIdx.x * 128;
#pragma unroll
    for (int i = 0; i < 8; i++) {
        int r = rbase + ((i < 4) ? (ty * 4 + i) : (64 + ty * 4 + (i - 4)));
        float* Cp = C + (size_t)r * N + cbase;
        *(float4*)(Cp + tx * 4)      = make_float4(acc[i][0], acc[i][1], acc[i][2], acc[i][3]);
        *(float4*)(Cp + 64 + tx * 4) = make_float4(acc[i][4], acc[i][5], acc[i][6], acc[i][7]);
    }
}

// ---------------- fused RMSNorm + RoPE (+ optional per-head gain) ---------
// one block (128 threads) per (token,head); in-place on X with row stride heads*128
__global__ void normrope_kernel(float* __restrict__ X, int heads,
                                const float* __restrict__ gain, int use_gain) {
    const int row = blockIdx.x;         // b*T + t
    const int h = blockIdx.y;
    const int d = threadIdx.x;          // 0..127
    const int ld = heads * DD;
    float* p = X + (size_t)row * ld + h * DD;

    float v = p[d];
    __shared__ float sh[DD];
    __shared__ float red[4];
    float sq = v * v;
#pragma unroll
    for (int o = 16; o; o >>= 1) sq += __shfl_xor_sync(0xffffffffu, sq, o);
    if ((d & 31) == 0) red[d >> 5] = sq;
    __syncthreads();
    float tot = red[0] + red[1] + red[2] + red[3];
    float r = rsqrtf(tot * (1.0f / DD) + 1.1920929e-7f);
    sh[d] = v * r;
    __syncthreads();
    if (d < HALF) {
        int t = row & (TT - 1);
        float c = g_cos[t * HALF + d];
        float s = g_sin[t * HALF + d];
        float x1 = sh[d], x2 = sh[d + HALF];
        float g = use_gain ? gain[h] : 1.0f;
        p[d]        = (x1 * c + x2 * s) * g;
        p[d + HALF] = (-x1 * s + x2 * c) * g;
    }
}

// ---------------- flash attention (causal, GQA) ---------------------------
// grid: (T/64, B*H); 256 threads; BM=BN=64, D=128; fp32, online softmax.
#define AT_BM 64
#define AT_BN 64
#define SS_LD 68
#define FLASH_SMEM ((3 * AT_BM * DD + AT_BM * SS_LD + 3 * AT_BM) * 4)

__global__ __launch_bounds__(256, 1)
void flash_attn_kernel(const float* __restrict__ Q, const float* __restrict__ K,
                       const float* __restrict__ V, float* __restrict__ O) {
    extern __shared__ __align__(16) float sm[];
    float* Qs = sm;                       // 64*128
    float* Ks = Qs + AT_BM * DD;          // 64*128
    float* Vs = Ks + AT_BN * DD;          // 64*128
    float* Ss = Vs + AT_BN * DD;          // 64*68
    float* mrow = Ss + AT_BM * SS_LD;     // 64
    float* lrow = mrow + AT_BM;           // 64
    float* arow = lrow + AT_BM;           // 64

    const int qb = blockIdx.x;
    const int bh = blockIdx.y;
    const int b = bh / HH;
    const int h = bh % HH;
    const int kh = h / GG;
    const int q0 = qb * AT_BM;
    const int tid = threadIdx.x;
    const int tx = tid & 15;
    const int ty = tid >> 4;
    const float scale = 0.08838834764831845f;   // 1/sqrt(128)

    // load Q tile, pre-scaled
    const float* Qbase = Q + ((size_t)(b * TT + q0)) * DIMn + h * DD;
#pragma unroll
    for (int i = tid; i < AT_BM * DD / 4; i += 256) {
        int r = i >> 5, c4 = (i & 31) << 2;
        float4 qv = *(const float4*)(Qbase + (size_t)r * DIMn + c4);
        qv.x *= scale; qv.y *= scale; qv.z *= scale; qv.w *= scale;
        *(float4*)(Qs + r * DD + c4) = qv;
    }
    if (tid < AT_BM) { mrow[tid] = -INFINITY; lrow[tid] = 0.f; }

    float acc[4][8];
#pragma unroll
    for (int i = 0; i < 4; i++)
#pragma unroll
        for (int j = 0; j < 8; j++) acc[i][j] = 0.f;

    const int nkb = qb + 1;
    for (int kb = 0; kb < nkb; kb++) {
        const int k0 = kb * AT_BN;
        __syncthreads();   // prior iter done reading Ks/Vs/Ss
        const float* Kbase = K + ((size_t)(b * TT + k0)) * KVD + kh * DD;
        const float* Vbase = V + ((size_t)(b * TT + k0)) * KVD + kh * DD;
#pragma unroll
        for (int i = tid; i < AT_BN * DD / 4; i += 256) {
            int r = i >> 5, c4 = (i & 31) << 2;
            *(float4*)(Ks + r * DD + c4) = *(const float4*)(Kbase + (size_t)r * KVD + c4);
            *(float4*)(Vs + r * DD + c4) = *(const float4*)(Vbase + (size_t)r * KVD + c4);
        }
        __syncthreads();

        // S = Qs * Ks^T  (each thread 4x4)
        float s[4][4];
#pragma unroll
        for (int i = 0; i < 4; i++)
#pragma unroll
            for (int j = 0; j < 4; j++) s[i][j] = 0.f;
        for (int k = 0; k < DD; k += 4) {
            float4 qv[4], kv[4];
#pragma unroll
            for (int i = 0; i < 4; i++) qv[i] = *(const float4*)(Qs + (ty * 4 + i) * DD + k);
#pragma unroll
            for (int j = 0; j < 4; j++) kv[j] = *(const float4*)(Ks + (tx * 4 + j) * DD + k);
#pragma unroll
            for (int i = 0; i < 4; i++)
#pragma unroll
                for (int j = 0; j < 4; j++)
                    s[i][j] += qv[i].x * kv[j].x + qv[i].y * kv[j].y +
                               qv[i].z * kv[j].z + qv[i].w * kv[j].w;
        }
        if (kb == qb) {   // diagonal block: causal mask
#pragma unroll
            for (int i = 0; i < 4; i++)
#pragma unroll
                for (int j = 0; j < 4; j++)
                    if ((tx * 4 + j) > (ty * 4 + i)) s[i][j] = -INFINITY;
        }
#pragma unroll
        for (int i = 0; i < 4; i++)
#pragma unroll
            for (int j = 0; j < 4; j++)
                Ss[(ty * 4 + i) * SS_LD + tx * 4 + j] = s[i][j];
        __syncthreads();

        // online softmax per row (threads 0..63)
        if (tid < AT_BM) {
            float m_old = mrow[tid];
            float m_new = m_old;
            float* rowp = Ss + tid * SS_LD;
#pragma unroll 8
            for (int c = 0; c < AT_BN; c++) m_new = fmaxf(m_new, rowp[c]);
            float alpha = expf(m_old - m_new);
            float lsum = 0.f;
#pragma unroll 8
            for (int c = 0; c < AT_BN; c++) {
                float pv = expf(rowp[c] - m_new);
                rowp[c] = pv;
                lsum += pv;
            }
            lrow[tid] = lrow[tid] * alpha + lsum;
            mrow[tid] = m_new;
            arow[tid] = alpha;
        }
        __syncthreads();

        // O = O*alpha + P @ V  (each thread rows ty*4..+3, cols tx*8..+7)
#pragma unroll
        for (int i = 0; i < 4; i++) {
            float al = arow[ty * 4 + i];
#pragma unroll
            for (int j = 0; j < 8; j++) acc[i][j] *= al;
        }
        for (int k = 0; k < AT_BN; k++) {
            float4 v0 = *(const float4*)(Vs + k * DD + tx * 8);
            float4 v1 = *(const float4*)(Vs + k * DD + tx * 8 + 4);
            float p0 = Ss[(ty * 4 + 0) * SS_LD + k];
            float p1 = Ss[(ty * 4 + 1) * SS_LD + k];
            float p2 = Ss[(ty * 4 + 2) * SS_LD + k];
            float p3 = Ss[(ty * 4 + 3) * SS_LD + k];
            acc[0][0] += p0 * v0.x; acc[0][1] += p0 * v0.y; acc[0][2] += p0 * v0.z; acc[0][3] += p0 * v0.w;
            acc[0][4] += p0 * v1.x; acc[0][5] += p0 * v1.y; acc[0][6] += p0 * v1.z; acc[0][7] += p0 * v1.w;
            acc[1][0] += p1 * v0.x; acc[1][1] += p1 * v0.y; acc[1][2] += p1 * v0.z; acc[1][3] += p1 * v0.w;
            acc[1][4] += p1 * v1.x; acc[1][5] += p1 * v1.y; acc[1][6] += p1 * v1.z; acc[1][7] += p1 * v1.w;
            acc[2][0] += p2 * v0.x; acc[2][1] += p2 * v0.y; acc[2][2] += p2 * v0.z; acc[2][3] += p2 * v0.w;
            acc[2][4] += p2 * v1.x; acc[2][5] += p2 * v1.y; acc[2][6] += p2 * v1.z; acc[2][7] += p2 * v1.w;
            acc[3][0] += p3 * v0.x; acc[3][1] += p3 * v0.y; acc[3][2] += p3 * v0.z; acc[3][3] += p3 * v0.w;
            acc[3][4] += p3 * v1.x; acc[3][5] += p3 * v1.y; acc[3][6] += p3 * v1.z; acc[3][7] += p3 * v1.w;
        }
    }

    // epilogue: divide by l, write out
    float* Obase = O + ((size_t)(b * TT + q0)) * DIMn + h * DD;
#pragma unroll
    for (int i = 0; i < 4; i++) {
        int r = ty * 4 + i;
        float inv_l = 1.0f / lrow[r];
        float4 o0 = make_float4(acc[i][0] * inv_l, acc[i][1] * inv_l,
                                acc[i][2] * inv_l, acc[i][3] * inv_l);
        float4 o1 = make_float4(acc[i][4] * inv_l, acc[i][5] * inv_l,
                                acc[i][6] * inv_l, acc[i][7] * inv_l);
        *(float4*)(Obase + (size_t)r * DIMn + tx * 8)     = o0;
        *(float4*)(Obase + (size_t)r * DIMn + tx * 8 + 4) = o1;
    }
}

// ---------------- host launcher ----------------
extern "C" void kernel_launch(void* const* d_in, const int* in_sizes, int n_in,
                              void* d_out, int out_size) {
    const float* x     = (const float*)d_in[0];
    const float* Wq    = (const float*)d_in[1];
    const float* Wk    = (const float*)d_in[2];
    const float* Wv    = (const float*)d_in[3];
    const float* Wproj = (const float*)d_in[4];
    const float* qgain = (const float*)d_in[5];
    float* out = (float*)d_out;

    float *q_ptr, *k_ptr, *y_ptr;
    cudaGetSymbolAddress((void**)&q_ptr, g_Q);
    cudaGetSymbolAddress((void**)&k_ptr, g_K);
    cudaGetSymbolAddress((void**)&y_ptr, g_Y);

    float* v_out = out + (size_t)NTOK * DIMn;   // v is the second output

    // 1. RoPE tables
    rope_table_kernel<<<(TT * HALF + 255) / 256, 256>>>();

    // 2. QKV projections (V written directly into output tail)
    sgemm_nt<<<dim3(DIMn / 128, NTOK / 128), 256>>>(x, Wq, q_ptr, NTOK, DIMn, DIMn);
    sgemm_nt<<<dim3(KVD / 128, NTOK / 128), 256>>>(x, Wk, k_ptr, NTOK, KVD, DIMn);
    sgemm_nt<<<dim3(KVD / 128, NTOK / 128), 256>>>(x, Wv, v_out, NTOK, KVD, DIMn);

    // 3. RMSNorm + RoPE (+ q gain)
    normrope_kernel<<<dim3(NTOK, HH), 128>>>(q_ptr, HH, qgain, 1);
    normrope_kernel<<<dim3(NTOK, HKVn), 128>>>(k_ptr, HKVn, nullptr, 0);

    // 4. causal GQA flash attention
    cudaFuncSetAttribute(flash_attn_kernel,
                         cudaFuncAttributeMaxDynamicSharedMemorySize, FLASH_SMEM);
    flash_attn_kernel<<<dim3(TT / AT_BM, BB * HH), 256, FLASH_SMEM>>>(q_ptr, k_ptr, v_out, y_ptr);

    // 5. output projection
    sgemm_nt<<<dim3(DIMn / 128, NTOK / 128), 256>>>(y_ptr, Wproj, out, NTOK, DIMn, DIMn);
}

// round 5
// speedup vs baseline: 1.1245x; 1.1245x over previous
#include <cuda_runtime.h>
#include <math.h>

// ---------------- problem constants ----------------
#define BB   2
#define TT   2048
#define HH   16
#define HKVn 4
#define DD   128
#define GG   4
#define DIMn 2048           // HH*DD
#define KVD  512            // HKVn*DD
#define NTOK (BB*TT)        // 4096
#define HALF 64             // DD/2

// ---------------- device scratch (no allocs allowed) ----------------
__device__ float g_Q[(size_t)NTOK * DIMn];     // 32 MB
__device__ float g_K[(size_t)NTOK * KVD];      // 8 MB
__device__ float g_Y[(size_t)NTOK * DIMn];     // 32 MB
__device__ float g_cos[TT * HALF];
__device__ float g_sin[TT * HALF];

// ---------------- small helpers ----------------
__device__ __forceinline__ float ex2(float x) {
    float r; asm("ex2.approx.ftz.f32 %0, %1;" : "=f"(r) : "f"(x)); return r;
}
__device__ __forceinline__ void cpa16(float* dst_smem, const float* src_gmem) {
    unsigned d = (unsigned)__cvta_generic_to_shared(dst_smem);
    asm volatile("cp.async.cg.shared.global [%0], [%1], 16;" :: "r"(d), "l"(src_gmem));
}
#define CP_COMMIT() asm volatile("cp.async.commit_group;" ::: "memory")

// ---------------- RoPE table (NTK-scaled, T > train_seq_len) ----------------
__global__ void rope_table_kernel() {
    int idx = blockIdx.x * blockDim.x + threadIdx.x;
    if (idx >= TT * HALF) return;
    int t = idx >> 6;          // token
    int i = idx & 63;          // pair index
    // base = 10000 * (T/1024)^(D/(D-2)) = 10000 * 2^(128/126)
    double base = 10000.0 * pow(2.0, 128.0 / 126.0);
    double inv  = pow(base, -((double)(2 * i)) / 128.0);
    double ang  = (double)t * inv;
    g_cos[idx] = (float)cos(ang);
    g_sin[idx] = (float)sin(ang);
}

// ---------------- SGEMM tile body: C[128,128] += A[128,K] * B[128,K]^T -----
// double-buffered smem, reg prefetch, 256 threads, 8x8 microtile (4+4 split)
__device__ __forceinline__ void gemm_tile_128(
    const float* __restrict__ Ab, const float* __restrict__ Bb,
    float* __restrict__ Cp, int K, int N,
    float (*As)[16][128], float (*Bs)[16][128])
{
    const int tid = threadIdx.x;
    const int tx = tid & 15;
    const int ty = tid >> 4;
    const int lr = tid >> 2;           // 0..63
    const int lc = (tid & 3) << 2;     // 0,4,8,12

    float acc[8][8];
#pragma unroll
    for (int i = 0; i < 8; i++)
#pragma unroll
        for (int j = 0; j < 8; j++) acc[i][j] = 0.f;

    // prologue: tile 0 -> buffer 0
    {
        float4 a0 = *(const float4*)(Ab + (size_t)lr * K + lc);
        float4 a1 = *(const float4*)(Ab + (size_t)(lr + 64) * K + lc);
        float4 b0 = *(const float4*)(Bb + (size_t)lr * K + lc);
        float4 b1 = *(const float4*)(Bb + (size_t)(lr + 64) * K + lc);
        As[0][lc + 0][lr] = a0.x; As[0][lc + 1][lr] = a0.y; As[0][lc + 2][lr] = a0.z; As[0][lc + 3][lr] = a0.w;
        As[0][lc + 0][lr + 64] = a1.x; As[0][lc + 1][lr + 64] = a1.y; As[0][lc + 2][lr + 64] = a1.z; As[0][lc + 3][lr + 64] = a1.w;
        Bs[0][lc + 0][lr] = b0.x; Bs[0][lc + 1][lr] = b0.y; Bs[0][lc + 2][lr] = b0.z; Bs[0][lc + 3][lr] = b0.w;
        Bs[0][lc + 0][lr + 64] = b1.x; Bs[0][lc + 1][lr + 64] = b1.y; Bs[0][lc + 2][lr + 64] = b1.z; Bs[0][lc + 3][lr + 64] = b1.w;
    }
    __syncthreads();

    const int KT = K >> 4;
    for (int kt = 0; kt < KT; kt++) {
        const int cur = kt & 1;
        float4 na0, na1, nb0, nb1;
        const bool more = (kt + 1 < KT);
        if (more) {
            const float* Ap = Ab + (size_t)lr * K + ((kt + 1) << 4) + lc;
            const float* Bp = Bb + (size_t)lr * K + ((kt + 1) << 4) + lc;
            na0 = *(const float4*)Ap;
            na1 = *(const float4*)(Ap + (size_t)64 * K);
            nb0 = *(const float4*)Bp;
            nb1 = *(const float4*)(Bp + (size_t)64 * K);
        }
#pragma unroll
        for (int kk = 0; kk < 16; kk++) {
            float4 xa0 = *(const float4*)&As[cur][kk][ty * 4];
            float4 xa1 = *(const float4*)&As[cur][kk][ty * 4 + 64];
            float4 xb0 = *(const float4*)&Bs[cur][kk][tx * 4];
            float4 xb1 = *(const float4*)&Bs[cur][kk][tx * 4 + 64];
            float av[8] = {xa0.x, xa0.y, xa0.z, xa0.w, xa1.x, xa1.y, xa1.z, xa1.w};
            float bv[8] = {xb0.x, xb0.y, xb0.z, xb0.w, xb1.x, xb1.y, xb1.z, xb1.w};
#pragma unroll
            for (int i = 0; i < 8; i++)
#pragma unroll
                for (int j = 0; j < 8; j++) acc[i][j] += av[i] * bv[j];
        }
        if (more) {
            const int nxt = cur ^ 1;
            As[nxt][lc + 0][lr] = na0.x; As[nxt][lc + 1][lr] = na0.y; As[nxt][lc + 2][lr] = na0.z; As[nxt][lc + 3][lr] = na0.w;
            As[nxt][lc + 0][lr + 64] = na1.x; As[nxt][lc + 1][lr + 64] = na1.y; As[nxt][lc + 2][lr + 64] = na1.z; As[nxt][lc + 3][lr + 64] = na1.w;
            Bs[nxt][lc + 0][lr] = nb0.x; Bs[nxt][lc + 1][lr] = nb0.y; Bs[nxt][lc + 2][lr] = nb0.z; Bs[nxt][lc + 3][lr] = nb0.w;
            Bs[nxt][lc + 0][lr + 64] = nb1.x; Bs[nxt][lc + 1][lr + 64] = nb1.y; Bs[nxt][lc + 2][lr + 64] = nb1.z; Bs[nxt][lc + 3][lr + 64] = nb1.w;
            __syncthreads();
        }
    }

#pragma unroll
    for (int i = 0; i < 8; i++) {
        int r = (i < 4) ? (ty * 4 + i) : (64 + ty * 4 + (i - 4));
        float* cp = Cp + (size_t)r * N;
        *(float4*)(cp + tx * 4)      = make_float4(acc[i][0], acc[i][1], acc[i][2], acc[i][3]);
        *(float4*)(cp + 64 + tx * 4) = make_float4(acc[i][4], acc[i][5], acc[i][6], acc[i][7]);
    }
}

__global__ __launch_bounds__(256, 2)
void sgemm_nt(const float* __restrict__ A, const float* __restrict__ Bm,
              float* __restrict__ C, int M, int N, int K) {
    __shared__ __align__(16) float As[2][16][128];
    __shared__ __align__(16) float Bs[2][16][128];
    gemm_tile_128(A + (size_t)blockIdx.y * 128 * K,
                  Bm + (size_t)blockIdx.x * 128 * K,
                  C + (size_t)blockIdx.y * 128 * N + blockIdx.x * 128,
                  K, N, As, Bs);
}

// fused K/V projection: grid.x = 8 (4 K col-blocks then 4 V col-blocks)
__global__ __launch_bounds__(256, 2)
void sgemm_kv(const float* __restrict__ x,
              const float* __restrict__ Wk, const float* __restrict__ Wv,
              float* __restrict__ Ck, float* __restrict__ Cv) {
    __shared__ __align__(16) float As[2][16][128];
    __shared__ __align__(16) float Bs[2][16][128];
    int nb = blockIdx.x;
    const float* Bsel;
    float* Csel;
    if (nb < 4) { Bsel = Wk; Csel = Ck; }
    else        { Bsel = Wv; Csel = Cv; nb -= 4; }
    gemm_tile_128(x + (size_t)blockIdx.y * 128 * DIMn,
                  Bsel + (size_t)nb * 128 * DIMn,
                  Csel + (size_t)blockIdx.y * 128 * KVD + nb * 128,
                  DIMn, KVD, As, Bs);
}

// ---------------- fused RMSNorm + RoPE (+ optional per-head gain) ---------
__global__ void normrope_kernel(float* __restrict__ X, int heads,
                                const float* __restrict__ gain, int use_gain) {
    const int row = blockIdx.x;         // b*T + t
    const int h = blockIdx.y;
    const int d = threadIdx.x;          // 0..127
    const int ld = heads * DD;
    float* p = X + (size_t)row * ld + h * DD;

    float v = p[d];
    __shared__ float sh[DD];
    __shared__ float red[4];
    float sq = v * v;
#pragma unroll
    for (int o = 16; o; o >>= 1) sq += __shfl_xor_sync(0xffffffffu, sq, o);
    if ((d & 31) == 0) red[d >> 5] = sq;
    __syncthreads();
    float tot = red[0] + red[1] + red[2] + red[3];
    float r = rsqrtf(tot * (1.0f / DD) + 1.1920929e-7f);
    sh[d] = v * r;
    __syncthreads();
    if (d < HALF) {
        int t = row & (TT - 1);
        float c = g_cos[t * HALF + d];
        float s = g_sin[t * HALF + d];
        float x1 = sh[d], x2 = sh[d + HALF];
        float g = use_gain ? gain[h] : 1.0f;
        p[d]        = (x1 * c + x2 * s) * g;
        p[d + HALF] = (-x1 * s + x2 * c) * g;
    }
}

// ---------------- flash attention (causal, GQA) ---------------------------
// grid: (T/64, B*H); 256 threads; BM=BN=64, D=128; fp32 SIMT.
// Register-resident online softmax (exp2 domain), cp.async double-buffered K/V.
#define AT_BM 64
#define AT_BN 64
#define SS_LD 68
// Qs(8192) + Ks[2](16384) + Vs[2](16384) + Ss(64*68)
#define FL_SMEM ((64 * 128 * 5 + 64 * SS_LD) * 4)

__global__ __launch_bounds__(256, 1)
void flash_attn_kernel(const float* __restrict__ Q, const float* __restrict__ K,
                       const float* __restrict__ V, float* __restrict__ O) {
    extern __shared__ __align__(16) float sm[];
    float* Qs  = sm;                 // 64*128
    float* Ks0 = sm + 8192;
    float* Ks1 = sm + 16384;
    float* Vs0 = sm + 24576;
    float* Vs1 = sm + 32768;
    float* Ss  = sm + 40960;         // 64*68

    const int qb = blockIdx.x;
    const int bh = blockIdx.y;
    const int b = bh / HH;
    const int h = bh % HH;
    const int kh = h / GG;
    const int q0 = qb * AT_BM;
    const int tid = threadIdx.x;
    const int tx = tid & 15;
    const int ty = tid >> 4;
    // 1/sqrt(128) * log2(e): softmax computed in exp2 domain
    const float qscale = 0.08838834764831845f * 1.4426950408889634f;

    // load Q tile (pre-scaled)
    const float* Qb = Q + ((size_t)(b * TT + q0)) * DIMn + h * DD;
    for (int i = tid; i < AT_BM * DD / 4; i += 256) {
        int r = i >> 5, c4 = (i & 31) << 2;
        float4 qv = *(const float4*)(Qb + (size_t)r * DIMn + c4);
        qv.x *= qscale; qv.y *= qscale; qv.z *= qscale; qv.w *= qscale;
        *(float4*)(Qs + r * DD + c4) = qv;
    }

    // prologue: async-load K/V block 0 into buffer 0
    const float* Kb = K + ((size_t)(b * TT)) * KVD + kh * DD;
    const float* Vb = V + ((size_t)(b * TT)) * KVD + kh * DD;
    for (int i = tid; i < AT_BN * DD / 4; i += 256) {
        int r = i >> 5, c4 = (i & 31) << 2;
        cpa16(Ks0 + r * DD + c4, Kb + (size_t)r * KVD + c4);
        cpa16(Vs0 + r * DD + c4, Vb + (size_t)r * KVD + c4);
    }
    CP_COMMIT();

    float m_run[4] = {-INFINITY, -INFINITY, -INFINITY, -INFINITY};
    float l_run[4] = {0.f, 0.f, 0.f, 0.f};
    float acc[4][8];
#pragma unroll
    for (int i = 0; i < 4; i++)
#pragma unroll
        for (int j = 0; j < 8; j++) acc[i][j] = 0.f;

    const int nkb = qb + 1;
    for (int kb = 0; kb < nkb; kb++) {
        const int cur = kb & 1;
        float* Ksc = cur ? Ks1 : Ks0;
        float* Vsc = cur ? Vs1 : Vs0;
        float* Ksn = cur ? Ks0 : Ks1;
        float* Vsn = cur ? Vs0 : Vs1;

        __syncthreads();   // prior iter done reading next buffer + Ss
        if (kb + 1 < nkb) {
            const float* Kn = Kb + (size_t)(kb + 1) * AT_BN * KVD;
            const float* Vn = Vb + (size_t)(kb + 1) * AT_BN * KVD;
            for (int i = tid; i < AT_BN * DD / 4; i += 256) {
                int r = i >> 5, c4 = (i & 31) << 2;
                cpa16(Ksn + r * DD + c4, Kn + (size_t)r * KVD + c4);
                cpa16(Vsn + r * DD + c4, Vn + (size_t)r * KVD + c4);
            }
            CP_COMMIT();
            asm volatile("cp.async.wait_group 1;" ::: "memory");
        } else {
            asm volatile("cp.async.wait_group 0;" ::: "memory");
        }
        __syncthreads();   // current buffer visible to all

        // S = Qs * Ks^T  (each thread 4x4)
        float s[4][4];
#pragma unroll
        for (int i = 0; i < 4; i++)
#pragma unroll
            for (int j = 0; j < 4; j++) s[i][j] = 0.f;
        for (int k = 0; k < DD; k += 4) {
            float4 qv[4], kv[4];
#pragma unroll
            for (int i = 0; i < 4; i++) qv[i] = *(const float4*)(Qs + (ty * 4 + i) * DD + k);
#pragma unroll
            for (int j = 0; j < 4; j++) kv[j] = *(const float4*)(Ksc + (tx * 4 + j) * DD + k);
#pragma unroll
            for (int i = 0; i < 4; i++)
#pragma unroll
                for (int j = 0; j < 4; j++)
                    s[i][j] += qv[i].x * kv[j].x + qv[i].y * kv[j].y +
                               qv[i].z * kv[j].z + qv[i].w * kv[j].w;
        }
        if (kb == qb) {   // diagonal block: causal mask
#pragma unroll
            for (int i = 0; i < 4; i++)
#pragma unroll
                for (int j = 0; j < 4; j++)
                    if ((tx * 4 + j) > (ty * 4 + i)) s[i][j] = -INFINITY;
        }

        // register online softmax: reduce over the 16 lanes sharing each row
#pragma unroll
        for (int i = 0; i < 4; i++) {
            float mi = fmaxf(fmaxf(s[i][0], s[i][1]), fmaxf(s[i][2], s[i][3]));
            mi = fmaxf(mi, __shfl_xor_sync(0xffffffffu, mi, 1));
            mi = fmaxf(mi, __shfl_xor_sync(0xffffffffu, mi, 2));
            mi = fmaxf(mi, __shfl_xor_sync(0xffffffffu, mi, 4));
            mi = fmaxf(mi, __shfl_xor_sync(0xffffffffu, mi, 8));
            float m_new = fmaxf(m_run[i], mi);
            float alpha = ex2(m_run[i] - m_new);
            m_run[i] = m_new;
            float li = 0.f;
#pragma unroll
            for (int j = 0; j < 4; j++) {
                s[i][j] = ex2(s[i][j] - m_new);
                li += s[i][j];
            }
            li += __shfl_xor_sync(0xffffffffu, li, 1);
            li += __shfl_xor_sync(0xffffffffu, li, 2);
            li += __shfl_xor_sync(0xffffffffu, li, 4);
            li += __shfl_xor_sync(0xffffffffu, li, 8);
            l_run[i] = l_run[i] * alpha + li;
#pragma unroll
            for (int j = 0; j < 8; j++) acc[i][j] *= alpha;
        }

        // publish P
#pragma unroll
        for (int i = 0; i < 4; i++)
#pragma unroll
            for (int j = 0; j < 4; j++)
                Ss[(ty * 4 + i) * SS_LD + tx * 4 + j] = s[i][j];
        __syncthreads();

        // O += P @ V  (each thread rows ty*4..+3, cols tx*8..+7)
#pragma unroll 4
        for (int k = 0; k < AT_BN; k++) {
            float4 v0 = *(const float4*)(Vsc + k * DD + tx * 8);
            float4 v1 = *(const float4*)(Vsc + k * DD + tx * 8 + 4);
            float p0 = Ss[(ty * 4 + 0) * SS_LD + k];
            float p1 = Ss[(ty * 4 + 1) * SS_LD + k];
            float p2 = Ss[(ty * 4 + 2) * SS_LD + k];
            float p3 = Ss[(ty * 4 + 3) * SS_LD + k];
            acc[0][0] += p0 * v0.x; acc[0][1] += p0 * v0.y; acc[0][2] += p0 * v0.z; acc[0][3] += p0 * v0.w;
            acc[0][4] += p0 * v1.x; acc[0][5] += p0 * v1.y; acc[0][6] += p0 * v1.z; acc[0][7] += p0 * v1.w;
            acc[1][0] += p1 * v0.x; acc[1][1] += p1 * v0.y; acc[1][2] += p1 * v0.z; acc[1][3] += p1 * v0.w;
            acc[1][4] += p1 * v1.x; acc[1][5] += p1 * v1.y; acc[1][6] += p1 * v1.z; acc[1][7] += p1 * v1.w;
            acc[2][0] += p2 * v0.x; acc[2][1] += p2 * v0.y; acc[2][2] += p2 * v0.z; acc[2][3] += p2 * v0.w;
            acc[2][4] += p2 * v1.x; acc[2][5] += p2 * v1.y; acc[2][6] += p2 * v1.z; acc[2][7] += p2 * v1.w;
            acc[3][0] += p3 * v0.x; acc[3][1] += p3 * v0.y; acc[3][2] += p3 * v0.z; acc[3][3] += p3 * v0.w;
            acc[3][4] += p3 * v1.x; acc[3][5] += p3 * v1.y; acc[3][6] += p3 * v1.z; acc[3][7] += p3 * v1.w;
        }
    }

    // epilogue: divide by l, write out
    float* Obase = O + ((size_t)(b * TT + q0)) * DIMn + h * DD;
#pragma unroll
    for (int i = 0; i < 4; i++) {
        int r = ty * 4 + i;
        float inv_l = 1.0f / l_run[i];
        float4 o0 = make_float4(acc[i][0] * inv_l, acc[i][1] * inv_l,
                                acc[i][2] * inv_l, acc[i][3] * inv_l);
        float4 o1 = make_float4(acc[i][4] * inv_l, acc[i][5] * inv_l,
                                acc[i][6] * inv_l, acc[i][7] * inv_l);
        *(float4*)(Obase + (size_t)r * DIMn + tx * 8)     = o0;
        *(float4*)(Obase + (size_t)r * DIMn + tx * 8 + 4) = o1;
    }
}

// ---------------- host launcher ----------------
extern "C" void kernel_launch(void* const* d_in, const int* in_sizes, int n_in,
                              void* d_out, int out_size) {
    const float* x     = (const float*)d_in[0];
    const float* Wq    = (const float*)d_in[1];
    const float* Wk    = (const float*)d_in[2];
    const float* Wv    = (const float*)d_in[3];
    const float* Wproj = (const float*)d_in[4];
    const float* qgain = (const float*)d_in[5];
    float* out = (float*)d_out;

    float *q_ptr, *k_ptr, *y_ptr;
    cudaGetSymbolAddress((void**)&q_ptr, g_Q);
    cudaGetSymbolAddress((void**)&k_ptr, g_K);
    cudaGetSymbolAddress((void**)&y_ptr, g_Y);

    float* v_out = out + (size_t)NTOK * DIMn;   // v is the second output

    // 1. RoPE tables
    rope_table_kernel<<<(TT * HALF + 255) / 256, 256>>>();

    // 2. QKV projections (V written directly into output tail; K/V fused)
    sgemm_nt<<<dim3(DIMn / 128, NTOK / 128), 256>>>(x, Wq, q_ptr, NTOK, DIMn, DIMn);
    sgemm_kv<<<dim3(8, NTOK / 128), 256>>>(x, Wk, Wv, k_ptr, v_out);

    // 3. RMSNorm + RoPE (+ q gain)
    normrope_kernel<<<dim3(NTOK, HH), 128>>>(q_ptr, HH, qgain, 1);
    normrope_kernel<<<dim3(NTOK, HKVn), 128>>>(k_ptr, HKVn, nullptr, 0);

    // 4. causal GQA flash attention
    cudaFuncSetAttribute(flash_attn_kernel,
                         cudaFuncAttributeMaxDynamicSharedMemorySize, FL_SMEM);
    flash_attn_kernel<<<dim3(TT / AT_BM, BB * HH), 256, FL_SMEM>>>(q_ptr, k_ptr, v_out, y_ptr);

    // 5. output projection
    sgemm_nt<<<dim3(DIMn / 128, NTOK / 128), 256>>>(y_ptr, Wproj, out, NTOK, DIMn, DIMn);
}